// round 3
// baseline (speedup 1.0000x reference)
#include <cuda_runtime.h>
#include <math.h>

#define T_ 1024
#define L_ 32
#define D_ 512
#define P_ 512
#define H_ 2048
#define SCALE_ 0.044194173824159216f  // 1/sqrt(512)
#define LN_EPS 1e-5f

// ---------------- scratch (device globals; no allocs allowed) ----------------
__device__ float g_bm[T_ * D_];          // base_mean [T,D]
__device__ float g_task_vec[P_];
__device__ float g_pooled_q[P_];
__device__ float g_u[D_];
__device__ float g_v[D_];
__device__ float g_dotu[T_];
__device__ float g_dotv[T_];
__device__ float g_coef[T_];
__device__ float g_fattn[L_ * L_];
__device__ __align__(16) float g_evolved[L_ * D_];
__device__ __align__(16) float g_aligned[L_ * D_];

// atomically-accumulated buffers, zeroed each launch (contiguous for fast zero)
#define A_RAWQ 0            // [32,512]  query without bias
#define A_WC   16384        // [32,512]  weighted conditioned (= weighted_prompts)
#define A_WK   32768        // [32,512]  wc@Wk (no bias)
#define A_WV   49152        // [32,512]  wc@Wv (no bias)
#define A_EP   65536        // [32,512]  fattn@wv (no bias)
#define A_OACC 81920        // [32,512]  (ep+bv)@Wo (no bias)
#define A_MLP  98304        // [32,512]  relu(h1+ba1)@Wa2 (no bias)
#define A_FLOG 114688       // [32,32]
#define A_H1   115712       // [32,2048] evolved@Wa1 (no bias)
#define ACC_TOTAL 181248
__device__ float g_acc[ACC_TOTAL];

// output layout offsets (floats)
#define OFF_ALIGNED 0
#define OFF_AP      16384
#define OFF_TW      16793600
#define OFF_FA      16794624

// ---------------- reduction helpers ----------------
__device__ __forceinline__ float warp_sum(float v) {
#pragma unroll
    for (int o = 16; o > 0; o >>= 1) v += __shfl_xor_sync(0xffffffffu, v, o);
    return v;
}
__device__ __forceinline__ float warp_max(float v) {
#pragma unroll
    for (int o = 16; o > 0; o >>= 1) v = fmaxf(v, __shfl_xor_sync(0xffffffffu, v, o));
    return v;
}
__device__ float blk_sum(float v, float* red) {
    int w = threadIdx.x >> 5, lane = threadIdx.x & 31;
    int nw = blockDim.x >> 5;
    v = warp_sum(v);
    if (lane == 0) red[w] = v;
    __syncthreads();
    if (w == 0) {
        float r = (lane < nw) ? red[lane] : 0.f;
        r = warp_sum(r);
        if (lane == 0) red[0] = r;
    }
    __syncthreads();
    float out = red[0];
    __syncthreads();
    return out;
}
__device__ float blk_max(float v, float* red) {
    int w = threadIdx.x >> 5, lane = threadIdx.x & 31;
    int nw = blockDim.x >> 5;
    v = warp_max(v);
    if (lane == 0) red[w] = v;
    __syncthreads();
    if (w == 0) {
        float r = (lane < nw) ? red[lane] : -3.4e38f;
        r = warp_max(r);
        if (lane == 0) red[0] = r;
    }
    __syncthreads();
    float out = red[0];
    __syncthreads();
    return out;
}

// ---------------- kernels ----------------

// zero accumulators + task_vec = tanh(te @ Wt + bt)
__global__ void k_prep(const float* __restrict__ te, const float* __restrict__ Wt,
                       const float* __restrict__ bt) {
    int b = blockIdx.x;
    if (b < 64) {
        for (int i = b * 512 + threadIdx.x; i < ACC_TOTAL; i += 64 * 512) g_acc[i] = 0.f;
    } else {
        __shared__ float tes[D_];
        tes[threadIdx.x] = te[threadIdx.x];
        __syncthreads();
        if (threadIdx.x < 64) {
            int p = (b - 64) * 64 + threadIdx.x;
            float acc = 0.f;
#pragma unroll 8
            for (int d = 0; d < D_; d++) acc += tes[d] * Wt[d * P_ + p];
            g_task_vec[p] = tanhf(acc + bt[p]);
        }
    }
}

// base_mean[t,d] = mean over L
__global__ void k_base_mean(const float* __restrict__ base) {
    int t = blockIdx.x, d = threadIdx.x;
    const float* p = base + (size_t)t * (L_ * D_) + d;
    float s = 0.f;
#pragma unroll
    for (int l = 0; l < L_; l++) s += p[l * D_];
    g_bm[t * D_ + d] = s * (1.0f / L_);
}

// generic [32,K] @ [K,N] split-K GEMM with atomic accumulation
// grid (N/64, K/KC), block 256 (64 cols x 4 row-groups of 8)
template <int KC>
__global__ void k_gemm32(const float* __restrict__ X, const float* __restrict__ W,
                         float* __restrict__ OUT, int K, int N,
                         const float* __restrict__ prebias, int dorelu) {
    extern __shared__ float Xs[];  // [32][KC]
    int k0 = blockIdx.y * KC;
    int col = blockIdx.x * 64 + (threadIdx.x & 63);
    int lg = threadIdx.x >> 6;
    for (int idx = threadIdx.x; idx < 32 * KC; idx += 256) {
        int l = idx / KC, k = idx - l * KC;
        float v = X[l * K + k0 + k];
        if (prebias) v += prebias[k0 + k];
        if (dorelu) v = fmaxf(v, 0.f);
        Xs[idx] = v;
    }
    __syncthreads();
    float acc[8] = {0.f, 0.f, 0.f, 0.f, 0.f, 0.f, 0.f, 0.f};
    const float* Wp = W + (size_t)k0 * N + col;
    const float* xb = Xs + (lg * 8) * KC;
#pragma unroll 4
    for (int k = 0; k < KC; k++) {
        float w = Wp[(size_t)k * N];
#pragma unroll
        for (int j = 0; j < 8; j++) acc[j] = fmaf(xb[j * KC + k], w, acc[j]);
    }
#pragma unroll
    for (int j = 0; j < 8; j++) atomicAdd(&OUT[(lg * 8 + j) * N + col], acc[j]);
}

// pooled_q[p] = mean_l(rawq) + bq
__global__ void k_pooledq(const float* __restrict__ bq) {
    int p = threadIdx.x;
    float s = 0.f;
#pragma unroll
    for (int l = 0; l < L_; l++) s += g_acc[A_RAWQ + l * P_ + p];
    g_pooled_q[p] = s * (1.0f / L_) + bq[p];
}

// u = Wk @ task_vec, v = Wk @ pooled_q  (row-major matvecs, warp per row)
__global__ void k_uv(const float* __restrict__ Wk) {
    __shared__ float tv[P_], pq[P_];
    int tid = threadIdx.x;
    tv[tid] = g_task_vec[tid];
    pq[tid] = g_pooled_q[tid];
    __syncthreads();
    int w = tid >> 5, lane = tid & 31;
    int d = blockIdx.x * 16 + w;
    const float* row = Wk + (size_t)d * P_;
    float au = 0.f, av = 0.f;
#pragma unroll
    for (int i = 0; i < 16; i++) {
        float x = row[lane + 32 * i];
        au = fmaf(x, tv[lane + 32 * i], au);
        av = fmaf(x, pq[lane + 32 * i], av);
    }
    au = warp_sum(au);
    av = warp_sum(av);
    if (lane == 0) { g_u[d] = au; g_v[d] = av; }
}

// dotu[t] = base_mean[t]·u, dotv[t] = base_mean[t]·v (warp per t)
__global__ void k_dots() {
    __shared__ float us[D_], vs[D_];
    int tid = threadIdx.x;
    us[tid] = g_u[tid];
    vs[tid] = g_v[tid];
    __syncthreads();
    int w = tid >> 5, lane = tid & 31;
    int t = blockIdx.x * 16 + w;
    const float* row = g_bm + t * D_;
    float au = 0.f, av = 0.f;
#pragma unroll
    for (int i = 0; i < 16; i++) {
        float x = row[lane + 32 * i];
        au = fmaf(x, us[lane + 32 * i], au);
        av = fmaf(x, vs[lane + 32 * i], av);
    }
    au = warp_sum(au);
    av = warp_sum(av);
    if (lane == 0) { g_dotu[t] = au; g_dotv[t] = av; }
}

// softmaxes + task weight combination; one block of 1024 threads
__global__ void k_weights(const float* __restrict__ bk, float* __restrict__ out_tw) {
    __shared__ float red[32];
    int t = threadIdx.x;
    float p0 = (t < P_) ? bk[t] * g_task_vec[t] : 0.f;
    float c0 = blk_sum(p0, red);
    float p1 = (t < P_) ? bk[t] * g_pooled_q[t] : 0.f;
    float c1 = blk_sum(p1, red);

    float s1 = SCALE_ * (g_dotu[t] + c0);
    float m1 = blk_max(s1, red);
    float e1 = expf(s1 - m1);
    float Z1 = blk_sum(e1, red);
    float tw1 = e1 / Z1;

    float s2 = SCALE_ * ((1.f + tw1) * g_dotv[t] + c1);
    float m2 = blk_max(s2, red);
    float e2 = expf(s2 - m2);
    float Z2 = blk_sum(e2, red);
    float ta = e2 / Z2;

    float tw = 0.5f * (tw1 + ta);
    float S = blk_sum(tw, red);
    float tw2 = tw / fmaxf(S, 1e-6f);
    g_coef[t] = tw2 * (1.f + tw1);
    out_tw[t] = tw2;
}

// wc[l,d] += sum over t-chunk of coef[t]*base[t,l,d]; grid (8 tsplit, 32 l)
__global__ void k_wc(const float* __restrict__ base) {
    __shared__ float cs[128];
    int l = blockIdx.y, t0 = blockIdx.x * 128, d = threadIdx.x;
    if (threadIdx.x < 128) cs[threadIdx.x] = g_coef[t0 + threadIdx.x];
    __syncthreads();
    const float* p = base + (size_t)t0 * (L_ * D_) + l * D_ + d;
    float s = 0.f;
#pragma unroll 8
    for (int i = 0; i < 128; i++) s = fmaf(cs[i], p[(size_t)i * (L_ * D_)], s);
    atomicAdd(&g_acc[A_WC + l * D_ + d], s);
}

// flog[i,j] += sum over k-chunk of q[i,k]*wkb[j,k]; grid 16 ksplit, block 1024
__global__ void k_flog(const float* __restrict__ bq, const float* __restrict__ bk) {
    __shared__ float qs[32][32];
    __shared__ float ks[32][33];
    int k0 = blockIdx.x * 32;
    int i = threadIdx.x >> 5, j = threadIdx.x & 31;
    qs[i][j] = g_acc[A_RAWQ + i * P_ + k0 + j] + bq[k0 + j];
    ks[i][j] = g_acc[A_WK + i * P_ + k0 + j] + bk[k0 + j];
    __syncthreads();
    float a = 0.f;
#pragma unroll
    for (int kk = 0; kk < 32; kk++) a = fmaf(qs[i][kk], ks[j][kk], a);
    atomicAdd(&g_acc[A_FLOG + threadIdx.x], a);
}

// row softmax of scale*flog -> g_fattn and output
__global__ void k_fsoftmax(float* __restrict__ out_fa) {
    int i = threadIdx.x >> 5, j = threadIdx.x & 31;
    float x = SCALE_ * g_acc[A_FLOG + i * 32 + j];
    float m = warp_max(x);
    float e = expf(x - m);
    float s = warp_sum(e);
    float f = e / s;
    g_fattn[i * 32 + j] = f;
    out_fa[i * 32 + j] = f;
}

// LayerNorm: x = A + B + bias; y = LN(x)*g + b -> out1 (and out2 if non-null)
__global__ void k_ln(const float* __restrict__ A, const float* __restrict__ B,
                     const float* __restrict__ bias, const float* __restrict__ g,
                     const float* __restrict__ b, float* __restrict__ out1,
                     float* __restrict__ out2) {
    __shared__ float red[32];
    int l = blockIdx.x, d = threadIdx.x;
    float x = A[l * D_ + d] + B[l * D_ + d] + bias[d];
    float mean = blk_sum(x, red) * (1.0f / D_);
    float c = x - mean;
    float var = blk_sum(c * c, red) * (1.0f / D_);
    float y = c * rsqrtf(var + LN_EPS) * g[d] + b[d];
    out1[l * D_ + d] = y;
    if (out2) out2[l * D_ + d] = y;
}

// broadcast aligned [L,D] to [T,L,D] region of output (float4 streaming stores)
__global__ void k_bcast(float4* __restrict__ outp) {
    const float4* src = reinterpret_cast<const float4*>(g_aligned);
    int base = blockIdx.x * 2048;
    for (int i = threadIdx.x; i < 2048; i += 256) {
        int idx = base + i;
        outp[idx] = src[idx & 4095];
    }
}

// ---------------- launch ----------------
extern "C" void kernel_launch(void* const* d_in, const int* in_sizes, int n_in,
                              void* d_out, int out_size) {
    const float* base = (const float*)d_in[0];
    const float* np_  = (const float*)d_in[1];
    const float* te   = (const float*)d_in[2];
    const float* Wt   = (const float*)d_in[3];
    const float* bt   = (const float*)d_in[4];
    const float* Wq   = (const float*)d_in[5];
    const float* bq   = (const float*)d_in[6];
    const float* Wk   = (const float*)d_in[7];
    const float* bk   = (const float*)d_in[8];
    const float* Wv   = (const float*)d_in[9];
    const float* bv   = (const float*)d_in[10];
    const float* Wo   = (const float*)d_in[11];
    const float* bo   = (const float*)d_in[12];
    const float* Wa1  = (const float*)d_in[13];
    const float* ba1  = (const float*)d_in[14];
    const float* Wa2  = (const float*)d_in[15];
    const float* ba2  = (const float*)d_in[16];
    const float* gin  = (const float*)d_in[17];
    const float* bin  = (const float*)d_in[18];
    const float* gout = (const float*)d_in[19];
    const float* bout = (const float*)d_in[20];
    float* out = (float*)d_out;

    float *acc, *fattnp, *evolvedp, *alignedp;
    cudaGetSymbolAddress((void**)&acc, g_acc);
    cudaGetSymbolAddress((void**)&fattnp, g_fattn);
    cudaGetSymbolAddress((void**)&evolvedp, g_evolved);
    cudaGetSymbolAddress((void**)&alignedp, g_aligned);

    k_prep<<<72, 512>>>(te, Wt, bt);
    k_base_mean<<<1024, 512>>>(base);
    // query (raw) = new_prompt @ Wq
    k_gemm32<128><<<dim3(8, 4), 256, 32 * 128 * 4>>>(np_, Wq, acc + A_RAWQ, 512, 512, nullptr, 0);
    k_pooledq<<<1, 512>>>(bq);
    k_uv<<<32, 512>>>(Wk);
    k_dots<<<64, 512>>>();
    k_weights<<<1, 1024>>>(bk, out + OFF_TW);
    k_wc<<<dim3(8, 32), 512>>>(base);
    k_gemm32<128><<<dim3(8, 4), 256, 32 * 128 * 4>>>(acc + A_WC, Wk, acc + A_WK, 512, 512, nullptr, 0);
    k_gemm32<128><<<dim3(8, 4), 256, 32 * 128 * 4>>>(acc + A_WC, Wv, acc + A_WV, 512, 512, nullptr, 0);
    k_flog<<<16, 1024>>>(bq, bk);
    k_fsoftmax<<<1, 1024>>>(out + OFF_FA);
    // evolved_proj (raw) = fattn @ wv_raw   (bv folded into next GEMM's prebias)
    k_gemm32<32><<<dim3(8, 1), 256, 32 * 32 * 4>>>(fattnp, acc + A_WV, acc + A_EP, 32, 512, nullptr, 0);
    // o_acc = (ep + bv) @ Wo
    k_gemm32<128><<<dim3(8, 4), 256, 32 * 128 * 4>>>(acc + A_EP, Wo, acc + A_OACC, 512, 512, bv, 0);
    // evolved = LN(wc + o_acc + bo)
    k_ln<<<32, 512>>>(acc + A_WC, acc + A_OACC, bo, gin, bin, evolvedp, nullptr);
    // h1 = evolved @ Wa1
    k_gemm32<128><<<dim3(32, 4), 256, 32 * 128 * 4>>>(evolvedp, Wa1, acc + A_H1, 512, 2048, nullptr, 0);
    // mlp = relu(h1 + ba1) @ Wa2
    k_gemm32<128><<<dim3(8, 16), 256, 32 * 128 * 4>>>(acc + A_H1, Wa2, acc + A_MLP, 2048, 512, ba1, 1);
    // aligned = LN(evolved + mlp + ba2) -> scratch + out[0:16384]
    k_ln<<<32, 512>>>(evolvedp, acc + A_MLP, ba2, gout, bout, alignedp, out + OFF_ALIGNED);
    k_bcast<<<2048, 256>>>((float4*)(out + OFF_AP));
}

// round 4
// speedup vs baseline: 1.4184x; 1.4184x over previous
#include <cuda_runtime.h>
#include <math.h>

#define T_ 1024
#define L_ 32
#define D_ 512
#define P_ 512
#define H_ 2048
#define NB 128
#define NT 256
#define SCALE_ 0.044194173824159216f  // 1/sqrt(512)
#define LN_EPS 1e-5f

// output layout offsets (floats)
#define OFF_ALIGNED 0
#define OFF_AP      16384
#define OFF_TW      16793600
#define OFF_FA      16794624

// ---------------- scratch (device globals; no allocs allowed) ----------------
__device__ float g_bm[T_ * D_];     // base_mean [T,D]
__device__ float g_rawq[L_ * P_];   // new_prompt @ Wq (no bias)
__device__ float g_tv[P_];          // task_vec
__device__ float g_pq[P_];          // pooled_q (with bias)
__device__ float g_u[D_];           // Wk @ task_vec
__device__ float g_v[D_];           // Wk @ pooled_q
__device__ float g_dotu[T_];
__device__ float g_dotv[T_];
__device__ float g_wc[L_ * D_];     // weighted conditioned (= weighted_prompts)
__device__ float g_wkr[L_ * P_];    // wc @ Wk (raw)
__device__ float g_wvr[L_ * P_];    // wc @ Wv (raw)
__device__ float g_flog[L_ * L_];   // scaled feature logits
__device__ float g_ep[L_ * P_];     // fattn @ wvr (raw)
__device__ float g_oacc[L_ * D_];   // (ep+bv) @ Wo
__device__ float g_evolved[L_ * D_];
__device__ float g_h1[L_ * H_];     // evolved @ Wa1 (raw)
__device__ float g_mlp0[L_ * D_];   // mlp partial k[0,1024)
__device__ float g_mlp1[L_ * D_];   // mlp partial k[1024,2048)
__device__ __align__(16) float g_aligned[L_ * D_];

// grid barrier state (zero-initialized; cnt returns to 0 each barrier, gen monotonic)
__device__ unsigned g_cnt;
__device__ unsigned g_gen;

// ---------------- grid barrier (all NB blocks resident: NB <= #SMs) ----------
__device__ __forceinline__ void gbar() {
    __threadfence();           // make this thread's global writes visible
    __syncthreads();           // all threads of block done + fenced
    if (threadIdx.x == 0) {
        unsigned gen = *(volatile unsigned*)&g_gen;
        if (atomicAdd(&g_cnt, 1u) == (unsigned)(NB - 1)) {
            g_cnt = 0u;
            __threadfence();
            *(volatile unsigned*)&g_gen = gen + 1u;
        } else {
            while (*(volatile unsigned*)&g_gen == gen) __nanosleep(32);
        }
    }
    __syncthreads();
}

// ---------------- reductions ----------------
__device__ __forceinline__ float warp_sum(float v) {
#pragma unroll
    for (int o = 16; o > 0; o >>= 1) v += __shfl_xor_sync(0xffffffffu, v, o);
    return v;
}
__device__ __forceinline__ float warp_max(float v) {
#pragma unroll
    for (int o = 16; o > 0; o >>= 1) v = fmaxf(v, __shfl_xor_sync(0xffffffffu, v, o));
    return v;
}
// block reductions for NT=256 (8 warps)
__device__ __forceinline__ float blk_sum(float v, float* red) {
    int w = threadIdx.x >> 5, lane = threadIdx.x & 31;
    v = warp_sum(v);
    if (lane == 0) red[w] = v;
    __syncthreads();
    if (w == 0) {
        float r = (lane < 8) ? red[lane] : 0.f;
        r = warp_sum(r);
        if (lane == 0) red[0] = r;
    }
    __syncthreads();
    float out = red[0];
    __syncthreads();
    return out;
}
__device__ __forceinline__ float blk_max(float v, float* red) {
    int w = threadIdx.x >> 5, lane = threadIdx.x & 31;
    v = warp_max(v);
    if (lane == 0) red[w] = v;
    __syncthreads();
    if (w == 0) {
        float r = (lane < 8) ? red[lane] : -3.4e38f;
        r = warp_max(r);
        if (lane == 0) red[0] = r;
    }
    __syncthreads();
    float out = red[0];
    __syncthreads();
    return out;
}

// ---------------- megakernel ----------------
__global__ void __launch_bounds__(NT, 1)
mega(const float* __restrict__ base, const float* __restrict__ np_,
     const float* __restrict__ te, const float* __restrict__ Wt,
     const float* __restrict__ bt, const float* __restrict__ Wq,
     const float* __restrict__ bq, const float* __restrict__ Wk,
     const float* __restrict__ bk, const float* __restrict__ Wv,
     const float* __restrict__ bv, const float* __restrict__ Wo,
     const float* __restrict__ bo, const float* __restrict__ Wa1,
     const float* __restrict__ ba1, const float* __restrict__ Wa2,
     const float* __restrict__ ba2, const float* __restrict__ gin,
     const float* __restrict__ bin, const float* __restrict__ gout,
     const float* __restrict__ bout, float* __restrict__ out) {
    __shared__ float sA[1024];
    __shared__ float sB[32];

    const int bid = blockIdx.x;
    const int tid = threadIdx.x;
    const int gtid = bid * NT + tid;
    const int w = tid >> 5, lane = tid & 31;

    // ============ S0: base_mean (all blocks) + rawq GEMM (blk 0-63) + task_vec (blk 64-65)
    {
#pragma unroll
        for (int it = 0; it < (T_ * D_) / (NB * NT); it++) {
            int o = gtid + it * NB * NT;
            int t = o >> 9, d = o & 511;
            const float* p = base + t * (L_ * D_) + d;
            float s = 0.f;
#pragma unroll
            for (int l = 0; l < L_; l++) s += p[l * D_];
            g_bm[o] = s * (1.f / L_);
        }
        if (bid < 64) {
            int o = gtid;                 // [0,16384)
            int l = o >> 9, p = o & 511;
            const float* xr = np_ + l * D_;
            const float* wcol = Wq + p;
            float a0 = 0.f, a1 = 0.f;
#pragma unroll 8
            for (int k = 0; k < D_; k += 2) {
                a0 = fmaf(xr[k], wcol[k * P_], a0);
                a1 = fmaf(xr[k + 1], wcol[(k + 1) * P_], a1);
            }
            g_rawq[o] = a0 + a1;
        } else if (bid < 66) {
            int p = ((bid - 64) << 8) + tid;
            const float* wcol = Wt + p;
            float a0 = 0.f, a1 = 0.f;
#pragma unroll 8
            for (int k = 0; k < D_; k += 2) {
                a0 = fmaf(te[k], wcol[k * P_], a0);
                a1 = fmaf(te[k + 1], wcol[(k + 1) * P_], a1);
            }
            g_tv[p] = tanhf(a0 + a1 + bt[p]);
        }
    }
    gbar();

    // ============ S1: pooled_q (per-block redundant) + u,v matvecs (blk 0-15)
    if (bid < 16) {
        for (int p = tid; p < P_; p += NT) sA[p] = g_tv[p];
        for (int p = tid; p < P_; p += NT) {
            float s = 0.f;
#pragma unroll
            for (int l = 0; l < L_; l++) s += g_rawq[l * P_ + p];
            float pq = s * (1.f / L_) + bq[p];
            sA[512 + p] = pq;
            if (bid == 0) g_pq[p] = pq;
        }
        __syncthreads();
#pragma unroll
        for (int r = 0; r < 4; r++) {
            int d = bid * 32 + w * 4 + r;
            const float* row = Wk + d * P_;
            float au = 0.f, av = 0.f;
#pragma unroll
            for (int i = 0; i < 16; i++) {
                float x = row[lane + 32 * i];
                au = fmaf(x, sA[lane + 32 * i], au);
                av = fmaf(x, sA[512 + lane + 32 * i], av);
            }
            au = warp_sum(au);
            av = warp_sum(av);
            if (lane == 0) { g_u[d] = au; g_v[d] = av; }
        }
    }
    gbar();

    // ============ S2: dots (warp per t; 128 blocks x 8 warps = 1024 warps)
    {
        int t = bid * 8 + w;
        const float* row = g_bm + t * D_;
        float au = 0.f, av = 0.f;
#pragma unroll
        for (int i = 0; i < 16; i++) {
            float x = row[lane + 32 * i];
            au = fmaf(x, g_u[lane + 32 * i], au);
            av = fmaf(x, g_v[lane + 32 * i], av);
        }
        au = warp_sum(au);
        av = warp_sum(av);
        if (lane == 0) { g_dotu[t] = au; g_dotv[t] = av; }
    }
    gbar();

    // ============ S3+S4: task-weight softmaxes (redundant per block) + wc combine (blk 0-63)
    if (bid < 64) {
        float p0 = 0.f, p1 = 0.f;
        for (int p = tid; p < P_; p += NT) {
            float bkp = bk[p];
            p0 = fmaf(bkp, g_tv[p], p0);
            p1 = fmaf(bkp, g_pq[p], p1);
        }
        float c0 = blk_sum(p0, sB);
        float c1 = blk_sum(p1, sB);

        float s1v[4], tw1v[4], dvv[4];
        float mymax = -3.4e38f;
#pragma unroll
        for (int i = 0; i < 4; i++) {
            int t = tid + 256 * i;
            s1v[i] = SCALE_ * (g_dotu[t] + c0);
            dvv[i] = g_dotv[t];
            mymax = fmaxf(mymax, s1v[i]);
        }
        float m1 = blk_max(mymax, sB);
        float es = 0.f;
#pragma unroll
        for (int i = 0; i < 4; i++) { s1v[i] = expf(s1v[i] - m1); es += s1v[i]; }
        float Z1 = blk_sum(es, sB);
        float invZ1 = 1.f / Z1;
#pragma unroll
        for (int i = 0; i < 4; i++) tw1v[i] = s1v[i] * invZ1;

        float s2v[4];
        mymax = -3.4e38f;
#pragma unroll
        for (int i = 0; i < 4; i++) {
            s2v[i] = SCALE_ * ((1.f + tw1v[i]) * dvv[i] + c1);
            mymax = fmaxf(mymax, s2v[i]);
        }
        float m2 = blk_max(mymax, sB);
        es = 0.f;
#pragma unroll
        for (int i = 0; i < 4; i++) { s2v[i] = expf(s2v[i] - m2); es += s2v[i]; }
        float Z2 = blk_sum(es, sB);
        float invZ2 = 1.f / Z2;

        float twv[4], Sp = 0.f;
#pragma unroll
        for (int i = 0; i < 4; i++) { twv[i] = 0.5f * (tw1v[i] + s2v[i] * invZ2); Sp += twv[i]; }
        float S = blk_sum(Sp, sB);
        float invS = 1.f / fmaxf(S, 1e-6f);
#pragma unroll
        for (int i = 0; i < 4; i++) {
            int t = tid + 256 * i;
            float tw2 = twv[i] * invS;
            sA[t] = tw2 * (1.f + tw1v[i]);       // coef[t]
            if (bid == 0) out[OFF_TW + t] = tw2;
        }
        __syncthreads();

        // wc[l,d] = sum_t coef[t] * base[t,l,d]  (this block: one l, 256 d's)
        int l = bid >> 1;
        int d = ((bid & 1) << 8) + tid;
        const float* bp = base + l * D_ + d;
        float a0 = 0.f, a1 = 0.f;
#pragma unroll 8
        for (int t = 0; t < T_; t += 2) {
            a0 = fmaf(sA[t], bp[t * (L_ * D_)], a0);
            a1 = fmaf(sA[t + 1], bp[(t + 1) * (L_ * D_)], a1);
        }
        g_wc[l * D_ + d] = a0 + a1;
    }
    gbar();

    // ============ S5: wkr = wc@Wk (blk 0-63), wvr = wc@Wv (blk 64-127)
    {
        int o = gtid & 16383;
        int l = o >> 9, p = o & 511;
        const float* W = (bid < 64) ? Wk : Wv;
        const float* xr = g_wc + l * D_;
        const float* wcol = W + p;
        float a0 = 0.f, a1 = 0.f;
#pragma unroll 8
        for (int k = 0; k < D_; k += 2) {
            a0 = fmaf(xr[k], wcol[k * P_], a0);
            a1 = fmaf(xr[k + 1], wcol[(k + 1) * P_], a1);
        }
        if (bid < 64) g_wkr[o] = a0 + a1;
        else          g_wvr[o] = a0 + a1;
    }
    gbar();

    // ============ S6: feature logits (blk 0-15; warp per output, lane-parallel k)
    if (bid < 16) {
        int l0 = bid * 2;
#pragma unroll
        for (int i = 0; i < 8; i++) {
            int oid = w + 8 * i;             // 0..63
            int l = l0 + (oid >> 5);
            int j = oid & 31;
            const float* qr = g_rawq + l * P_;
            const float* kr = g_wkr + j * P_;
            float a = 0.f;
#pragma unroll
            for (int ii = 0; ii < 16; ii++) {
                int k = lane + 32 * ii;
                a = fmaf(qr[k] + bq[k], kr[k] + bk[k], a);
            }
            a = warp_sum(a);
            if (lane == 0) g_flog[l * 32 + j] = SCALE_ * a;
        }
    }
    gbar();

    // ============ S7: fattn softmax (redundant per block) + ep = fattn@wvr (blk 0-63)
    if (bid < 64) {
#pragma unroll
        for (int r = 0; r < 4; r++) {
            int l = w * 4 + r;
            float x = g_flog[l * 32 + lane];
            float m = warp_max(x);
            float e = expf(x - m);
            float s = warp_sum(e);
            sA[l * 32 + lane] = e / s;
        }
        __syncthreads();
        if (bid == 0) {
#pragma unroll
            for (int i = 0; i < 4; i++) out[OFF_FA + tid + 256 * i] = sA[tid + 256 * i];
        }
        int o = gtid;
        int l = o >> 9, p = o & 511;
        const float* wv_ = g_wvr + p;
        float a = 0.f;
#pragma unroll
        for (int j = 0; j < 32; j++) a = fmaf(sA[l * 32 + j], wv_[j * P_], a);
        g_ep[o] = a;
    }
    gbar();

    // ============ S8: oacc = (ep+bv)@Wo (blk 0-63)
    if (bid < 64) {
        int o = gtid;
        int l = o >> 9, d = o & 511;
        const float* er = g_ep + l * P_;
        const float* wcol = Wo + d;
        float a0 = 0.f, a1 = 0.f;
#pragma unroll 8
        for (int k = 0; k < P_; k += 2) {
            a0 = fmaf(er[k] + bv[k], wcol[k * D_], a0);
            a1 = fmaf(er[k + 1] + bv[k + 1], wcol[(k + 1) * D_], a1);
        }
        g_oacc[o] = a0 + a1;
    }
    gbar();

    // ============ S9: LN1 -> evolved (blk 0-31, row per block)
    if (bid < 32) {
        int l = bid, d1 = tid + 256;
        float x0 = g_wc[l * D_ + tid] + g_oacc[l * D_ + tid] + bo[tid];
        float x1 = g_wc[l * D_ + d1] + g_oacc[l * D_ + d1] + bo[d1];
        float mean = blk_sum(x0 + x1, sB) * (1.f / D_);
        float c0 = x0 - mean, c1 = x1 - mean;
        float var = blk_sum(c0 * c0 + c1 * c1, sB) * (1.f / D_);
        float r = rsqrtf(var + LN_EPS);
        g_evolved[l * D_ + tid] = c0 * r * gin[tid] + bin[tid];
        g_evolved[l * D_ + d1] = c1 * r * gin[d1] + bin[d1];
    }
    gbar();

    // ============ S10: h1 = evolved@Wa1 (all blocks; 2 outputs/thread share W column)
    {
        int o = gtid;                    // [0,32768)
        int l = o >> 11, p = o & 2047;
        const float* xr0 = g_evolved + l * D_;
        const float* xr1 = g_evolved + (l + 16) * D_;
        const float* wcol = Wa1 + p;
        float a0 = 0.f, a1 = 0.f;
#pragma unroll 8
        for (int k = 0; k < D_; k++) {
            float ww = wcol[k * H_];
            a0 = fmaf(xr0[k], ww, a0);
            a1 = fmaf(xr1[k], ww, a1);
        }
        g_h1[l * H_ + p] = a0;
        g_h1[(l + 16) * H_ + p] = a1;
    }
    gbar();

    // ============ S11: mlp = relu(h1+ba1)@Wa2, split-K halves (no atomics)
    {
        int part = bid >> 6;                     // 0 or 1
        int o = ((bid & 63) << 8) + tid;         // [0,16384)
        int l = o >> 9, d = o & 511;
        int k0 = part << 10;
        const float* hr = g_h1 + l * H_;
        const float* wcol = Wa2 + d;
        float a0 = 0.f, a1 = 0.f;
#pragma unroll 8
        for (int k = k0; k < k0 + 1024; k += 2) {
            float h0 = fmaxf(hr[k] + ba1[k], 0.f);
            float h1v = fmaxf(hr[k + 1] + ba1[k + 1], 0.f);
            a0 = fmaf(h0, wcol[k * D_], a0);
            a1 = fmaf(h1v, wcol[(k + 1) * D_], a1);
        }
        if (part == 0) g_mlp0[o] = a0 + a1;
        else           g_mlp1[o] = a0 + a1;
    }
    gbar();

    // ============ S12: LN2 -> aligned (+ out[0:16384]) (blk 0-31)
    if (bid < 32) {
        int l = bid, d1 = tid + 256;
        float x0 = g_evolved[l * D_ + tid] + g_mlp0[l * D_ + tid] + g_mlp1[l * D_ + tid] + ba2[tid];
        float x1 = g_evolved[l * D_ + d1] + g_mlp0[l * D_ + d1] + g_mlp1[l * D_ + d1] + ba2[d1];
        float mean = blk_sum(x0 + x1, sB) * (1.f / D_);
        float c0 = x0 - mean, c1 = x1 - mean;
        float var = blk_sum(c0 * c0 + c1 * c1, sB) * (1.f / D_);
        float r = rsqrtf(var + LN_EPS);
        float y0 = c0 * r * gout[tid] + bout[tid];
        float y1 = c1 * r * gout[d1] + bout[d1];
        g_aligned[l * D_ + tid] = y0;
        g_aligned[l * D_ + d1] = y1;
        out[OFF_ALIGNED + l * D_ + tid] = y0;
        out[OFF_ALIGNED + l * D_ + d1] = y1;
    }
    gbar();

    // ============ S13: broadcast aligned -> out[T,L,D] (all blocks, float4)
    {
        const float4* src = reinterpret_cast<const float4*>(g_aligned);
        float4* dst = reinterpret_cast<float4*>(out + OFF_AP);
        const int total = (T_ * L_ * D_) / 4;    // 4194304
#pragma unroll 4
        for (int i = gtid; i < total; i += NB * NT) {
            dst[i] = src[i & 4095];
        }
    }
}

// ---------------- launch ----------------
extern "C" void kernel_launch(void* const* d_in, const int* in_sizes, int n_in,
                              void* d_out, int out_size) {
    (void)in_sizes; (void)n_in; (void)out_size;
    const float* base = (const float*)d_in[0];
    const float* np_  = (const float*)d_in[1];
    const float* te   = (const float*)d_in[2];
    const float* Wt   = (const float*)d_in[3];
    const float* bt   = (const float*)d_in[4];
    const float* Wq   = (const float*)d_in[5];
    const float* bq   = (const float*)d_in[6];
    const float* Wk   = (const float*)d_in[7];
    const float* bk   = (const float*)d_in[8];
    const float* Wv   = (const float*)d_in[9];
    const float* bv   = (const float*)d_in[10];
    const float* Wo   = (const float*)d_in[11];
    const float* bo   = (const float*)d_in[12];
    const float* Wa1  = (const float*)d_in[13];
    const float* ba1  = (const float*)d_in[14];
    const float* Wa2  = (const float*)d_in[15];
    const float* ba2  = (const float*)d_in[16];
    const float* gin  = (const float*)d_in[17];
    const float* bin  = (const float*)d_in[18];
    const float* gout = (const float*)d_in[19];
    const float* bout = (const float*)d_in[20];
    float* out = (float*)d_out;

    mega<<<NB, NT>>>(base, np_, te, Wt, bt, Wq, bq, Wk, bk, Wv, bv, Wo, bo,
                     Wa1, ba1, Wa2, ba2, gin, bin, gout, bout, out);
}

// round 9
// speedup vs baseline: 2.1634x; 1.5252x over previous
#include <cuda_runtime.h>
#include <math.h>

#define T_ 1024
#define L_ 32
#define D_ 512
#define P_ 512
#define H_ 2048
#define NB 128
#define NT 512
#define NTH (NB * NT)   // 65536
#define SCALE_ 0.044194173824159216f  // 1/sqrt(512)
#define LN_EPS 1e-5f
#define SMEM_BYTES 66560

// output layout offsets (floats)
#define OFF_ALIGNED 0
#define OFF_AP      16384
#define OFF_TW      16793600
#define OFF_FA      16794624

// ---------------- scratch (device globals; no allocs allowed) ----------------
__device__ __align__(16) float g_bm[T_ * D_];      // base_mean [T,D]
__device__ __align__(16) float g_rawq[L_ * P_];    // new_prompt @ Wq (no bias)
__device__ __align__(16) float g_tv[P_];           // task_vec
__device__ __align__(16) float g_pq[P_];           // pooled_q (with bias)
__device__ __align__(16) float g_u[D_];            // Wk @ task_vec
__device__ __align__(16) float g_v[D_];            // Wk @ pooled_q
__device__ __align__(16) float g_dotu[T_];
__device__ __align__(16) float g_dotv[T_];
__device__ __align__(16) float g_wcp[4 * L_ * D_]; // wc partials (4-way t split)
__device__ __align__(16) float g_wc[L_ * D_];      // weighted conditioned
__device__ __align__(16) float g_wkr[L_ * P_];     // wc @ Wk (raw)
__device__ __align__(16) float g_wvr[L_ * P_];     // wc @ Wv (raw)
__device__ __align__(16) float g_oacc[L_ * D_];    // (ep+bv) @ Wo
__device__ __align__(16) float g_evolved[L_ * D_];
__device__ __align__(16) float g_h1[L_ * H_];      // evolved @ Wa1 (raw)
__device__ __align__(16) float g_mlpp[4 * L_ * D_];// mlp partials (4-way k split)
__device__ __align__(16) float g_aligned[L_ * D_];

// grid barrier state
__device__ unsigned g_cnt;
__device__ unsigned g_gen;

// ---------------- grid barrier (all NB blocks resident) ----------------
__device__ __forceinline__ void gbar() {
    __threadfence();
    __syncthreads();
    if (threadIdx.x == 0) {
        unsigned gen = *(volatile unsigned*)&g_gen;
        if (atomicAdd(&g_cnt, 1u) == (unsigned)(NB - 1)) {
            g_cnt = 0u;
            __threadfence();
            *(volatile unsigned*)&g_gen = gen + 1u;
        } else {
            while (*(volatile unsigned*)&g_gen == gen) __nanosleep(32);
        }
    }
    __syncthreads();
}

// ---------------- reductions ----------------
__device__ __forceinline__ float warp_sum(float v) {
#pragma unroll
    for (int o = 16; o > 0; o >>= 1) v += __shfl_xor_sync(0xffffffffu, v, o);
    return v;
}
__device__ __forceinline__ float warp_max(float v) {
#pragma unroll
    for (int o = 16; o > 0; o >>= 1) v = fmaxf(v, __shfl_xor_sync(0xffffffffu, v, o));
    return v;
}
// block reductions for NT=512 (16 warps)
__device__ __forceinline__ float blk_sum(float v, float* red) {
    int w = threadIdx.x >> 5, lane = threadIdx.x & 31;
    v = warp_sum(v);
    if (lane == 0) red[w] = v;
    __syncthreads();
    if (w == 0) {
        float r = (lane < 16) ? red[lane] : 0.f;
        r = warp_sum(r);
        if (lane == 0) red[0] = r;
    }
    __syncthreads();
    float out = red[0];
    __syncthreads();
    return out;
}
__device__ __forceinline__ float blk_max(float v, float* red) {
    int w = threadIdx.x >> 5, lane = threadIdx.x & 31;
    v = warp_max(v);
    if (lane == 0) red[w] = v;
    __syncthreads();
    if (w == 0) {
        float r = (lane < 16) ? red[lane] : -3.4e38f;
        r = warp_max(r);
        if (lane == 0) red[0] = r;
    }
    __syncthreads();
    float out = red[0];
    __syncthreads();
    return out;
}
__device__ __forceinline__ float dot4(float4 a, float4 b) {
    return fmaf(a.x, b.x, fmaf(a.y, b.y, fmaf(a.z, b.z, a.w * b.w)));
}

// ---------------- megakernel ----------------
__global__ void __launch_bounds__(NT, 1)
mega(const float* __restrict__ base, const float* __restrict__ np_,
     const float* __restrict__ te, const float* __restrict__ Wt,
     const float* __restrict__ bt, const float* __restrict__ Wq,
     const float* __restrict__ bq, const float* __restrict__ Wk,
     const float* __restrict__ bk, const float* __restrict__ Wv,
     const float* __restrict__ bv, const float* __restrict__ Wo,
     const float* __restrict__ bo, const float* __restrict__ Wa1,
     const float* __restrict__ ba1, const float* __restrict__ Wa2,
     const float* __restrict__ ba2, const float* __restrict__ gin,
     const float* __restrict__ bin, const float* __restrict__ gout,
     const float* __restrict__ bout, float* __restrict__ out) {
    extern __shared__ float sm[];

    const int bid = blockIdx.x;
    const int tid = threadIdx.x;
    const int gtid = bid * NT + tid;
    const int w = tid >> 5, lane = tid & 31;
    const float4* base4 = reinterpret_cast<const float4*>(base);

    // ======== S0: base_mean (all, float4) + rawq (blk 0-31) + task_vec (blk 32)
    {
#pragma unroll
        for (int it = 0; it < 2; it++) {
            int o = gtid + it * NTH;
            int t = o >> 7, c = o & 127;
            const float4* p = base4 + t * 4096 + c;
            float4 s = {0.f, 0.f, 0.f, 0.f};
#pragma unroll 8
            for (int l = 0; l < L_; l++) {
                float4 b4 = p[l * 128];
                s.x += b4.x; s.y += b4.y; s.z += b4.z; s.w += b4.w;
            }
            s.x *= (1.f / L_); s.y *= (1.f / L_); s.z *= (1.f / L_); s.w *= (1.f / L_);
            reinterpret_cast<float4*>(g_bm)[o] = s;
        }
        if (bid < 32) {
            int o = gtid;                    // [0,16384)
            int l = o >> 9, p = o & 511;
            const float* xr = np_ + l * D_;
            const float* wcol = Wq + p;
            float a0 = 0.f, a1 = 0.f;
#pragma unroll 8
            for (int k = 0; k < D_; k += 2) {
                a0 = fmaf(xr[k], wcol[k * P_], a0);
                a1 = fmaf(xr[k + 1], wcol[(k + 1) * P_], a1);
            }
            g_rawq[o] = a0 + a1;
        } else if (bid == 32) {
            int p = tid;
            const float* wcol = Wt + p;
            float a0 = 0.f, a1 = 0.f;
#pragma unroll 8
            for (int k = 0; k < D_; k += 2) {
                a0 = fmaf(te[k], wcol[k * P_], a0);
                a1 = fmaf(te[k + 1], wcol[(k + 1) * P_], a1);
            }
            g_tv[p] = tanhf(a0 + a1 + bt[p]);
        }
    }
    gbar();

    // ======== S1: pooled_q + u,v matvecs (blk 0-15)
    if (bid < 16) {
        float* sTV = sm;
        float* sPQ = sm + 512;
        sTV[tid] = g_tv[tid];
        {
            float s = 0.f;
#pragma unroll
            for (int l = 0; l < L_; l++) s += g_rawq[l * P_ + tid];
            float pq = s * (1.f / L_) + bq[tid];
            sPQ[tid] = pq;
            if (bid == 0) g_pq[tid] = pq;
        }
        __syncthreads();
        const float4* tv4 = reinterpret_cast<const float4*>(sTV);
        const float4* pq4 = reinterpret_cast<const float4*>(sPQ);
#pragma unroll
        for (int r = 0; r < 2; r++) {
            int d = bid * 32 + w * 2 + r;
            const float4* row = reinterpret_cast<const float4*>(Wk + (size_t)d * P_);
            float au = 0.f, av = 0.f;
#pragma unroll
            for (int i = 0; i < 4; i++) {
                float4 x = row[lane + 32 * i];
                au += dot4(x, tv4[lane + 32 * i]);
                av += dot4(x, pq4[lane + 32 * i]);
            }
            au = warp_sum(au);
            av = warp_sum(av);
            if (lane == 0) { g_u[d] = au; g_v[d] = av; }
        }
    }
    gbar();

    // ======== S2: dots (blk 0-63, warp per t)
    if (bid < 64) {
        int t = bid * 16 + w;
        const float4* row = reinterpret_cast<const float4*>(g_bm) + t * 128;
        const float4* u4 = reinterpret_cast<const float4*>(g_u);
        const float4* v4 = reinterpret_cast<const float4*>(g_v);
        float au = 0.f, av = 0.f;
#pragma unroll
        for (int i = 0; i < 4; i++) {
            float4 x = row[lane + 32 * i];
            au += dot4(x, u4[lane + 32 * i]);
            av += dot4(x, v4[lane + 32 * i]);
        }
        au = warp_sum(au);
        av = warp_sum(av);
        if (lane == 0) { g_dotu[t] = au; g_dotv[t] = av; }
    }
    gbar();

    // ======== S3: task softmaxes (redundant) + wc partials (all blocks)
    {
        float* sC = sm;                // 1024 coef
        float* sRed = sm + 1024;       // 32
        float4* sP4 = reinterpret_cast<float4*>(sm + 1088);  // 512 float4

        float bkp = bk[tid];
        float c0 = blk_sum(bkp * g_tv[tid], sRed);
        float c1 = blk_sum(bkp * g_pq[tid], sRed);

        float s1v[2], tw1v[2], dvv[2];
        float mymax = -3.4e38f;
#pragma unroll
        for (int i = 0; i < 2; i++) {
            int t = tid + 512 * i;
            s1v[i] = SCALE_ * (g_dotu[t] + c0);
            dvv[i] = g_dotv[t];
            mymax = fmaxf(mymax, s1v[i]);
        }
        float m1 = blk_max(mymax, sRed);
        float es = 0.f;
#pragma unroll
        for (int i = 0; i < 2; i++) { s1v[i] = expf(s1v[i] - m1); es += s1v[i]; }
        float invZ1 = 1.f / blk_sum(es, sRed);
#pragma unroll
        for (int i = 0; i < 2; i++) tw1v[i] = s1v[i] * invZ1;

        float s2v[2];
        mymax = -3.4e38f;
#pragma unroll
        for (int i = 0; i < 2; i++) {
            s2v[i] = SCALE_ * ((1.f + tw1v[i]) * dvv[i] + c1);
            mymax = fmaxf(mymax, s2v[i]);
        }
        float m2 = blk_max(mymax, sRed);
        es = 0.f;
#pragma unroll
        for (int i = 0; i < 2; i++) { s2v[i] = expf(s2v[i] - m2); es += s2v[i]; }
        float invZ2 = 1.f / blk_sum(es, sRed);

        float twv[2], Sp = 0.f;
#pragma unroll
        for (int i = 0; i < 2; i++) { twv[i] = 0.5f * (tw1v[i] + s2v[i] * invZ2); Sp += twv[i]; }
        float invS = 1.f / fmaxf(blk_sum(Sp, sRed), 1e-6f);
#pragma unroll
        for (int i = 0; i < 2; i++) {
            int t = tid + 512 * i;
            float tw2 = twv[i] * invS;
            sC[t] = tw2 * (1.f + tw1v[i]);
            if (bid == 0) out[OFF_TW + t] = tw2;
        }
        __syncthreads();

        // wc partial: block (l = bid>>2, q = bid&3); thread (c = tid&127, ts = tid>>7)
        int l = bid >> 2, q = bid & 3;
        int c = tid & 127, ts = tid >> 7;
        int t0 = q * 256 + ts * 64;
        const float4* bp = base4 + (size_t)t0 * 4096 + l * 128 + c;
        const float* cf = sC + t0;
        float4 acc = {0.f, 0.f, 0.f, 0.f};
#pragma unroll 8
        for (int i = 0; i < 64; i++) {
            float cv = cf[i];
            float4 b4 = bp[i * 4096];
            acc.x = fmaf(cv, b4.x, acc.x);
            acc.y = fmaf(cv, b4.y, acc.y);
            acc.z = fmaf(cv, b4.z, acc.z);
            acc.w = fmaf(cv, b4.w, acc.w);
        }
        sP4[ts * 128 + c] = acc;
        __syncthreads();
        if (tid < 128) {
            float4 a = sP4[tid], b = sP4[128 + tid], cc = sP4[256 + tid], d = sP4[384 + tid];
            a.x += b.x + cc.x + d.x;
            a.y += b.y + cc.y + d.y;
            a.z += b.z + cc.z + d.z;
            a.w += b.w + cc.w + d.w;
            reinterpret_cast<float4*>(g_wcp)[q * 4096 + l * 128 + tid] = a;
        }
    }
    gbar();

    // ======== S4: fold wc + wkr/wvr (blk 0-63)
    if (bid < 64) {
        float* sX = sm;
        int l = bid & 31;
        float x = g_wcp[l * 512 + tid] + g_wcp[16384 + l * 512 + tid] +
                  g_wcp[32768 + l * 512 + tid] + g_wcp[49152 + l * 512 + tid];
        sX[tid] = x;
        if (bid < 32) g_wc[l * 512 + tid] = x;
        __syncthreads();
        const float* W = (bid < 32) ? Wk : Wv;
        const float* wcol = W + tid;
        float a0 = 0.f, a1 = 0.f;
#pragma unroll 8
        for (int k = 0; k < D_; k += 2) {
            a0 = fmaf(sX[k], wcol[k * P_], a0);
            a1 = fmaf(sX[k + 1], wcol[(k + 1) * P_], a1);
        }
        if (bid < 32) g_wkr[l * 512 + tid] = a0 + a1;
        else          g_wvr[l * 512 + tid] = a0 + a1;
    }
    gbar();

    // ======== S5: flog + softmax + ep + oacc (all blocks; l = bid>>2, dq = bid&3)
    {
        float* sF = sm;          // 32
        float* sFa = sm + 32;    // 32
        float* sE = sm + 64;     // 512
        float* sP = sm + 576;    // 512
        int l = bid >> 2, dq = bid & 3;
        const float* qr = g_rawq + l * P_;
#pragma unroll
        for (int rr = 0; rr < 2; rr++) {
            int j = w + 16 * rr;
            const float* kr = g_wkr + j * P_;
            float a = 0.f;
#pragma unroll
            for (int i = 0; i < 16; i++) {
                int e = lane + 32 * i;
                a = fmaf(qr[e] + bq[e], kr[e] + bk[e], a);
            }
            a = warp_sum(a);
            if (lane == 0) sF[j] = SCALE_ * a;
        }
        __syncthreads();
        if (w == 0) {
            float x = sF[lane];
            float m = warp_max(x);
            float e = expf(x - m);
            float s = warp_sum(e);
            float f = e / s;
            sFa[lane] = f;
            if (dq == 0) out[OFF_FA + l * 32 + lane] = f;
        }
        __syncthreads();
        {
            float a = bv[tid];
#pragma unroll
            for (int j = 0; j < 32; j++) a = fmaf(sFa[j], g_wvr[j * P_ + tid], a);
            sE[tid] = a;
        }
        __syncthreads();
        {
            int dd = tid & 127, ks = tid >> 7;
            int d = dq * 128 + dd;
            const float* wcol = Wo + d;
            float a0 = 0.f, a1 = 0.f;
#pragma unroll 8
            for (int kk = 0; kk < 128; kk += 2) {
                int k = ks * 128 + kk;
                a0 = fmaf(sE[k], wcol[k * D_], a0);
                a1 = fmaf(sE[k + 1], wcol[(k + 1) * D_], a1);
            }
            sP[ks * 128 + dd] = a0 + a1;
        }
        __syncthreads();
        if (tid < 128)
            g_oacc[l * 512 + dq * 128 + tid] =
                sP[tid] + sP[128 + tid] + sP[256 + tid] + sP[384 + tid];
    }
    gbar();

    // ======== S6: LN1 (redundant, warp-per-row) + h1 (all blocks, 16-col strip)
    {
        float* sEvo = sm;   // 16384 floats = 64KB
#pragma unroll
        for (int rr = 0; rr < 2; rr++) {
            int row = w + 16 * rr;
            float x[16];
            float s = 0.f;
#pragma unroll
            for (int i = 0; i < 16; i++) {
                int e = lane + 32 * i;
                x[i] = g_wc[row * 512 + e] + g_oacc[row * 512 + e] + bo[e];
                s += x[i];
            }
            float mean = warp_sum(s) * (1.f / D_);
            float v = 0.f;
#pragma unroll
            for (int i = 0; i < 16; i++) { float d = x[i] - mean; v = fmaf(d, d, v); }
            float inv = rsqrtf(warp_sum(v) * (1.f / D_) + LN_EPS);
#pragma unroll
            for (int i = 0; i < 16; i++) {
                int e = lane + 32 * i;
                sEvo[row * 512 + e] = (x[i] - mean) * inv * gin[e] + bin[e];
            }
        }
        __syncthreads();
        if (bid == 0)
            for (int i = tid; i < 16384; i += NT) g_evolved[i] = sEvo[i];
        int l = tid >> 4;
        int p = (bid << 4) + (tid & 15);
        const float* wcol = Wa1 + p;
        const float* xr = sEvo + l * 512;
        float a0 = 0.f, a1 = 0.f;
#pragma unroll 8
        for (int k = 0; k < D_; k += 2) {
            a0 = fmaf(xr[k], wcol[(size_t)k * H_], a0);
            a1 = fmaf(xr[k + 1], wcol[(size_t)(k + 1) * H_], a1);
        }
        g_h1[l * H_ + p] = a0 + a1;
    }
    gbar();

    // ======== S7: mlp partials (all blocks; ks = bid&3, dseg = bid>>2)
    {
        float* sH = sm;   // 16384 floats = 64KB
        int ks = bid & 3, dseg = bid >> 2;
        for (int i = tid; i < 16384; i += NT) {
            int row = i >> 9, k = i & 511;
            int kg = ks * 512 + k;
            sH[i] = fmaxf(g_h1[row * H_ + kg] + ba1[kg], 0.f);
        }
        __syncthreads();
        int l = tid >> 4, dd = tid & 15;
        int d = dseg * 16 + dd;
        const float* wcol = Wa2 + (size_t)ks * 512 * D_ + d;
        const float* hr = sH + l * 512;
        float a0 = 0.f, a1 = 0.f;
#pragma unroll 8
        for (int k = 0; k < 512; k += 2) {
            a0 = fmaf(hr[k], wcol[(size_t)k * D_], a0);
            a1 = fmaf(hr[k + 1], wcol[(size_t)(k + 1) * D_], a1);
        }
        g_mlpp[ks * 16384 + l * 512 + d] = a0 + a1;
    }
    gbar();

    // ======== S8: LN2 -> aligned + out[0:16384] (blk 0-31)
    if (bid < 32) {
        float* sRed = sm;
        int l = bid;
        float x = g_evolved[l * 512 + tid] + g_mlpp[l * 512 + tid] +
                  g_mlpp[16384 + l * 512 + tid] + g_mlpp[32768 + l * 512 + tid] +
                  g_mlpp[49152 + l * 512 + tid] + ba2[tid];
        float mean = blk_sum(x, sRed) * (1.f / D_);
        float c = x - mean;
        float var = blk_sum(c * c, sRed) * (1.f / D_);
        float y = c * rsqrtf(var + LN_EPS) * gout[tid] + bout[tid];
        g_aligned[l * 512 + tid] = y;
        out[OFF_ALIGNED + l * 512 + tid] = y;
    }
    gbar();

    // ======== S9: broadcast aligned -> out[T,L,D] (all blocks; 1 src val, 64 stores)
    {
        const float4 v = reinterpret_cast<const float4*>(g_aligned)[gtid & 4095];
        float4* dst = reinterpret_cast<float4*>(out + OFF_AP);
#pragma unroll 8
        for (int k2 = 0; k2 < 64; k2++) dst[gtid + k2 * NTH] = v;
    }
}

// ---------------- launch ----------------
extern "C" void kernel_launch(void* const* d_in, const int* in_sizes, int n_in,
                              void* d_out, int out_size) {
    (void)in_sizes; (void)n_in; (void)out_size;
    const float* base = (const float*)d_in[0];
    const float* np_  = (const float*)d_in[1];
    const float* te   = (const float*)d_in[2];
    const float* Wt   = (const float*)d_in[3];
    const float* bt   = (const float*)d_in[4];
    const float* Wq   = (const float*)d_in[5];
    const float* bq   = (const float*)d_in[6];
    const float* Wk   = (const float*)d_in[7];
    const float* bk   = (const float*)d_in[8];
    const float* Wv   = (const float*)d_in[9];
    const float* bv   = (const float*)d_in[10];
    const float* Wo   = (const float*)d_in[11];
    const float* bo   = (const float*)d_in[12];
    const float* Wa1  = (const float*)d_in[13];
    const float* ba1  = (const float*)d_in[14];
    const float* Wa2  = (const float*)d_in[15];
    const float* ba2  = (const float*)d_in[16];
    const float* gin  = (const float*)d_in[17];
    const float* bin  = (const float*)d_in[18];
    const float* gout = (const float*)d_in[19];
    const float* bout = (const float*)d_in[20];
    float* out = (float*)d_out;

    static int attr_done = 0;
    if (!attr_done) {
        cudaFuncSetAttribute(mega, cudaFuncAttributeMaxDynamicSharedMemorySize, SMEM_BYTES);
        attr_done = 1;
    }
    mega<<<NB, NT, SMEM_BYTES>>>(base, np_, te, Wt, bt, Wq, bq, Wk, bk, Wv, bv,
                                 Wo, bo, Wa1, ba1, Wa2, ba2, gin, bin, gout, bout, out);
}

// round 11
// speedup vs baseline: 2.7913x; 1.2903x over previous
#include <cuda_runtime.h>
#include <math.h>

#define T_ 1024
#define L_ 32
#define D_ 512
#define P_ 512
#define H_ 2048
#define NB 128
#define NT 1024
#define NTH (NB * NT)   // 131072
#define SCALE_ 0.044194173824159216f  // 1/sqrt(512)
#define LN_EPS 1e-5f
#define SMEM_BYTES 70656

// output layout offsets (floats)
#define OFF_ALIGNED 0
#define OFF_AP      16384
#define OFF_TW      16793600
#define OFF_FA      16794624

// ---------------- scratch (device globals) ----------------
__device__ __align__(16) float g_bm[T_ * D_];       // base_mean [T,D]
__device__ __align__(16) float g_rawqp[4 * L_ * P_];// rawq partials (4-way k)
__device__ __align__(16) float g_rawq[L_ * P_];     // new_prompt @ Wq (no bias)
__device__ __align__(16) float g_tv[P_];            // task_vec
__device__ __align__(16) float g_pq[P_];            // pooled_q (with bias)
__device__ __align__(16) float g_u[D_];             // Wk @ task_vec
__device__ __align__(16) float g_v[D_];             // Wk @ pooled_q
__device__ __align__(16) float g_dotu[T_];
__device__ __align__(16) float g_dotv[T_];
__device__ __align__(16) float g_wcp[4 * L_ * D_];  // wc partials (4-way t)
__device__ __align__(16) float g_wc[L_ * D_];       // weighted conditioned
__device__ __align__(16) float g_wkr[L_ * P_];      // wc @ Wk (raw)
__device__ __align__(16) float g_wvr[L_ * P_];      // wc @ Wv (raw)
__device__ __align__(16) float g_oacc[L_ * D_];     // (ep+bv) @ Wo
__device__ __align__(16) float g_evolved[L_ * D_];
__device__ __align__(16) float g_h1[L_ * H_];       // evolved @ Wa1 (raw)
__device__ __align__(16) float g_mlpp[4 * L_ * D_]; // mlp partials (4-way k)

// grid barrier state
__device__ unsigned g_cnt;
__device__ unsigned g_gen;

// ---------------- grid barrier (all NB blocks resident) ----------------
__device__ __forceinline__ void gbar() {
    __threadfence();
    __syncthreads();
    if (threadIdx.x == 0) {
        unsigned gen = *(volatile unsigned*)&g_gen;
        if (atomicAdd(&g_cnt, 1u) == (unsigned)(NB - 1)) {
            g_cnt = 0u;
            __threadfence();
            *(volatile unsigned*)&g_gen = gen + 1u;
        } else {
            while (*(volatile unsigned*)&g_gen == gen) __nanosleep(32);
        }
    }
    __syncthreads();
}

// ---------------- reductions ----------------
__device__ __forceinline__ float warp_sum(float v) {
#pragma unroll
    for (int o = 16; o > 0; o >>= 1) v += __shfl_xor_sync(0xffffffffu, v, o);
    return v;
}
__device__ __forceinline__ float warp_max(float v) {
#pragma unroll
    for (int o = 16; o > 0; o >>= 1) v = fmaxf(v, __shfl_xor_sync(0xffffffffu, v, o));
    return v;
}
// block reductions for NT=1024 (32 warps)
__device__ __forceinline__ float blk_sum(float v, float* red) {
    int w = threadIdx.x >> 5, lane = threadIdx.x & 31;
    v = warp_sum(v);
    if (lane == 0) red[w] = v;
    __syncthreads();
    if (w == 0) {
        float r = red[lane];
        r = warp_sum(r);
        if (lane == 0) red[0] = r;
    }
    __syncthreads();
    float out = red[0];
    __syncthreads();
    return out;
}
__device__ __forceinline__ float blk_max(float v, float* red) {
    int w = threadIdx.x >> 5, lane = threadIdx.x & 31;
    v = warp_max(v);
    if (lane == 0) red[w] = v;
    __syncthreads();
    if (w == 0) {
        float r = red[lane];
        r = warp_max(r);
        if (lane == 0) red[0] = r;
    }
    __syncthreads();
    float out = red[0];
    __syncthreads();
    return out;
}
__device__ __forceinline__ float dot4(float4 a, float4 b) {
    return fmaf(a.x, b.x, fmaf(a.y, b.y, fmaf(a.z, b.z, a.w * b.w)));
}

// ---------------- megakernel ----------------
__global__ void __launch_bounds__(NT, 1)
mega(const float* __restrict__ base, const float* __restrict__ np_,
     const float* __restrict__ te, const float* __restrict__ Wt,
     const float* __restrict__ bt, const float* __restrict__ Wq,
     const float* __restrict__ bq, const float* __restrict__ Wk,
     const float* __restrict__ bk, const float* __restrict__ Wv,
     const float* __restrict__ bv, const float* __restrict__ Wo,
     const float* __restrict__ bo, const float* __restrict__ Wa1,
     const float* __restrict__ ba1, const float* __restrict__ Wa2,
     const float* __restrict__ ba2, const float* __restrict__ gin,
     const float* __restrict__ bin, const float* __restrict__ gout,
     const float* __restrict__ bout, float* __restrict__ out) {
    extern __shared__ float sm[];

    const int bid = blockIdx.x;
    const int tid = threadIdx.x;
    const int gtid = bid * NT + tid;
    const int w = tid >> 5, lane = tid & 31;
    const float4* base4 = reinterpret_cast<const float4*>(base);

    // ======== S0: base_mean (all; 1 float4/thread) + rawq partials (blk 0-63)
    //          + task_vec (blk 127)
    {
        {
            int o = gtid;                       // [0, 131072) = T*D/4
            int t = o >> 7, c = o & 127;
            const float4* p = base4 + t * 4096 + c;
            float4 s = {0.f, 0.f, 0.f, 0.f};
#pragma unroll 8
            for (int l = 0; l < L_; l++) {
                float4 b4 = p[l * 128];
                s.x += b4.x; s.y += b4.y; s.z += b4.z; s.w += b4.w;
            }
            s.x *= (1.f / L_); s.y *= (1.f / L_); s.z *= (1.f / L_); s.w *= (1.f / L_);
            reinterpret_cast<float4*>(g_bm)[o] = s;
        }
        if (bid < 64) {
            int task = bid * NT + tid;          // [0, 65536)
            int o = task & 16383, s = task >> 14;   // s in 0..3
            int l = o >> 9, p = o & 511;
            int k0 = s * 128;
            const float* xr = np_ + l * D_ + k0;
            const float* wcol = Wq + (size_t)k0 * P_ + p;
            float a0 = 0.f, a1 = 0.f;
#pragma unroll 8
            for (int k = 0; k < 128; k += 2) {
                a0 = fmaf(xr[k], wcol[(size_t)k * P_], a0);
                a1 = fmaf(xr[k + 1], wcol[(size_t)(k + 1) * P_], a1);
            }
            g_rawqp[s * 16384 + o] = a0 + a1;
        } else if (bid == 127) {
            float* sPart = sm;
            int p = tid & 511, kh = tid >> 9;
            const float* wcol = Wt + (size_t)(kh * 256) * P_ + p;
            const float* tr = te + kh * 256;
            float a0 = 0.f, a1 = 0.f;
#pragma unroll 8
            for (int k = 0; k < 256; k += 2) {
                a0 = fmaf(tr[k], wcol[(size_t)k * P_], a0);
                a1 = fmaf(tr[k + 1], wcol[(size_t)(k + 1) * P_], a1);
            }
            sPart[tid] = a0 + a1;
            __syncthreads();
            if (tid < 512) g_tv[tid] = tanhf(sPart[tid] + sPart[512 + tid] + bt[tid]);
        }
    }
    gbar();

    // ======== S1: rawq fold (blk 16-31) + pooled_q (redundant) + u,v (blk 0-15)
    if (bid < 16) {
        float* sPart = sm;            // 1024
        float* sTV = sm + 1024;       // 512
        float* sPQ = sm + 1536;       // 512
        if (tid < 512) sTV[tid] = g_tv[tid];
        {
            int p = tid & 511, half = tid >> 9;
            int l0 = half * 16;
            float a = 0.f;
#pragma unroll 4
            for (int l = 0; l < 16; l++) {
                int ro = (l0 + l) * 512 + p;
#pragma unroll
                for (int s = 0; s < 4; s++) a += g_rawqp[s * 16384 + ro];
            }
            sPart[tid] = a;
        }
        __syncthreads();
        if (tid < 512) {
            float pq = (sPart[tid] + sPart[512 + tid]) * (1.f / L_) + bq[tid];
            sPQ[tid] = pq;
            if (bid == 0) g_pq[tid] = pq;
        }
        __syncthreads();
        {
            int d = bid * 32 + w;
            const float4* row = reinterpret_cast<const float4*>(Wk + (size_t)d * P_);
            const float4* tv4 = reinterpret_cast<const float4*>(sTV);
            const float4* pq4 = reinterpret_cast<const float4*>(sPQ);
            float au = 0.f, av = 0.f;
#pragma unroll
            for (int i = 0; i < 4; i++) {
                float4 x = row[lane + 32 * i];
                au += dot4(x, tv4[lane + 32 * i]);
                av += dot4(x, pq4[lane + 32 * i]);
            }
            au = warp_sum(au);
            av = warp_sum(av);
            if (lane == 0) { g_u[d] = au; g_v[d] = av; }
        }
    } else if (bid < 32) {
        int o = (bid - 16) * NT + tid;    // [0,16384)
        g_rawq[o] = g_rawqp[o] + g_rawqp[16384 + o] + g_rawqp[32768 + o] + g_rawqp[49152 + o];
    }
    gbar();

    // ======== S2: dots (blk 0-31, warp per t)
    if (bid < 32) {
        int t = bid * 32 + w;
        const float4* row = reinterpret_cast<const float4*>(g_bm) + t * 128;
        const float4* u4 = reinterpret_cast<const float4*>(g_u);
        const float4* v4 = reinterpret_cast<const float4*>(g_v);
        float au = 0.f, av = 0.f;
#pragma unroll
        for (int i = 0; i < 4; i++) {
            float4 x = row[lane + 32 * i];
            au += dot4(x, u4[lane + 32 * i]);
            av += dot4(x, v4[lane + 32 * i]);
        }
        au = warp_sum(au);
        av = warp_sum(av);
        if (lane == 0) { g_dotu[t] = au; g_dotv[t] = av; }
    }
    gbar();

    // ======== S3: task softmaxes (redundant; tid==t) + wc partials (all blocks)
    {
        float* sC = sm;                // 1024 coef
        float* sRed = sm + 1024;       // 32
        float4* sP4 = reinterpret_cast<float4*>(sm + 1056); // 1024 float4

        float bt0 = (tid < 512) ? bk[tid] * g_tv[tid] : 0.f;
        float c0 = blk_sum(bt0, sRed);
        float bt1 = (tid < 512) ? bk[tid] * g_pq[tid] : 0.f;
        float c1 = blk_sum(bt1, sRed);

        float s1 = SCALE_ * (g_dotu[tid] + c0);
        float dv = g_dotv[tid];
        float m1 = blk_max(s1, sRed);
        float e1 = expf(s1 - m1);
        float tw1 = e1 / blk_sum(e1, sRed);

        float s2 = SCALE_ * ((1.f + tw1) * dv + c1);
        float m2 = blk_max(s2, sRed);
        float e2 = expf(s2 - m2);
        float ta = e2 / blk_sum(e2, sRed);

        float tw = 0.5f * (tw1 + ta);
        float S = blk_sum(tw, sRed);
        float tw2 = tw / fmaxf(S, 1e-6f);
        sC[tid] = tw2 * (1.f + tw1);
        if (bid == 0) out[OFF_TW + tid] = tw2;
        __syncthreads();

        // wc partial: block (l = bid>>2, q = bid&3); thread (c = tid&127, ts = tid>>7)
        int l = bid >> 2, q = bid & 3;
        int c = tid & 127, ts = tid >> 7;       // ts 0..7
        int t0 = q * 256 + ts * 32;
        const float4* bp = base4 + (size_t)t0 * 4096 + l * 128 + c;
        const float* cf = sC + t0;
        float4 acc = {0.f, 0.f, 0.f, 0.f};
#pragma unroll 8
        for (int i = 0; i < 32; i++) {
            float cv = cf[i];
            float4 b4 = bp[i * 4096];
            acc.x = fmaf(cv, b4.x, acc.x);
            acc.y = fmaf(cv, b4.y, acc.y);
            acc.z = fmaf(cv, b4.z, acc.z);
            acc.w = fmaf(cv, b4.w, acc.w);
        }
        sP4[ts * 128 + c] = acc;
        __syncthreads();
        if (tid < 128) {
            float4 a = sP4[tid];
#pragma unroll
            for (int g2 = 1; g2 < 8; g2++) {
                float4 b = sP4[g2 * 128 + tid];
                a.x += b.x; a.y += b.y; a.z += b.z; a.w += b.w;
            }
            reinterpret_cast<float4*>(g_wcp)[q * 4096 + l * 128 + tid] = a;
        }
    }
    gbar();

    // ======== S4: fold wc (redundant) + wkr/wvr column-strip GEMM (all blocks)
    {
        float* sX = sm;               // 32 x 513 padded
        float* sPart = sm + 16416;    // 1024
        const float* W = (bid < 64) ? Wk : Wv;
        int colbase = (bid & 63) * 8;
        for (int i = tid; i < 16384; i += NT) {
            float x = g_wcp[i] + g_wcp[16384 + i] + g_wcp[32768 + i] + g_wcp[49152 + i];
            int l = i >> 9, k = i & 511;
            sX[l * 513 + k] = x;
            if (bid == 0) g_wc[i] = x;
        }
        __syncthreads();
        int o = tid & 255;                  // l = o>>3, dd = o&7
        int l = o >> 3, dd = o & 7;
        int kq = tid >> 8;                  // 0..3
        const float* xr = sX + l * 513 + kq * 128;
        const float* wcol = W + (size_t)(kq * 128) * P_ + colbase + dd;
        float a0 = 0.f, a1 = 0.f;
#pragma unroll 8
        for (int k = 0; k < 128; k += 2) {
            a0 = fmaf(xr[k], wcol[(size_t)k * P_], a0);
            a1 = fmaf(xr[k + 1], wcol[(size_t)(k + 1) * P_], a1);
        }
        sPart[kq * 256 + o] = a0 + a1;
        __syncthreads();
        if (tid < 256) {
            float v = sPart[tid] + sPart[256 + tid] + sPart[512 + tid] + sPart[768 + tid];
            int ll = tid >> 3, d2 = tid & 7;
            if (bid < 64) g_wkr[ll * 512 + colbase + d2] = v;
            else          g_wvr[ll * 512 + colbase + d2] = v;
        }
    }
    gbar();

    // ======== S5: flog + softmax + ep + oacc (block = (l = bid>>2, dq = bid&3))
    {
        float* sF = sm;          // 32
        float* sFa = sm + 32;    // 32
        float* sE = sm + 64;     // 512
        float* sP = sm + 576;    // 1024
        int l = bid >> 2, dq = bid & 3;
        const float* qr = g_rawq + l * P_;
        {   // warp w computes flog[l][w]
            const float* kr = g_wkr + w * P_;
            float a = 0.f;
#pragma unroll
            for (int i = 0; i < 16; i++) {
                int e = lane + 32 * i;
                a = fmaf(qr[e] + bq[e], kr[e] + bk[e], a);
            }
            a = warp_sum(a);
            if (lane == 0) sF[w] = SCALE_ * a;
        }
        __syncthreads();
        if (w == 0) {
            float x = sF[lane];
            float m = warp_max(x);
            float e = expf(x - m);
            float s = warp_sum(e);
            float f = e / s;
            sFa[lane] = f;
            if (dq == 0) out[OFF_FA + l * 32 + lane] = f;
        }
        __syncthreads();
        if (tid < 512) {
            float a = bv[tid];
#pragma unroll
            for (int j = 0; j < 32; j++) a = fmaf(sFa[j], g_wvr[j * P_ + tid], a);
            sE[tid] = a;
        }
        __syncthreads();
        {
            int dd = tid & 127, ks = tid >> 7;  // ks 0..7
            int d = dq * 128 + dd;
            const float* wcol = Wo + (size_t)(ks * 64) * D_ + d;
            const float* er = sE + ks * 64;
            float a0 = 0.f, a1 = 0.f;
#pragma unroll 8
            for (int k = 0; k < 64; k += 2) {
                a0 = fmaf(er[k], wcol[(size_t)k * D_], a0);
                a1 = fmaf(er[k + 1], wcol[(size_t)(k + 1) * D_], a1);
            }
            sP[ks * 128 + dd] = a0 + a1;
        }
        __syncthreads();
        if (tid < 128) {
            float v = 0.f;
#pragma unroll
            for (int g2 = 0; g2 < 8; g2++) v += sP[g2 * 128 + tid];
            g_oacc[l * 512 + dq * 128 + tid] = v;
        }
    }
    gbar();

    // ======== S6: LN1 (redundant, warp-per-row) + h1 strip GEMM (all blocks)
    {
        float* sEvo = sm;             // 32 x 513
        float* sPart = sm + 16416;    // 1024
        {
            int row = w;
            float x[16];
            float s = 0.f;
#pragma unroll
            for (int i = 0; i < 16; i++) {
                int e = lane + 32 * i;
                x[i] = g_wc[row * 512 + e] + g_oacc[row * 512 + e] + bo[e];
                s += x[i];
            }
            float mean = warp_sum(s) * (1.f / D_);
            float v = 0.f;
#pragma unroll
            for (int i = 0; i < 16; i++) { float d = x[i] - mean; v = fmaf(d, d, v); }
            float inv = rsqrtf(warp_sum(v) * (1.f / D_) + LN_EPS);
#pragma unroll
            for (int i = 0; i < 16; i++) {
                int e = lane + 32 * i;
                float y = (x[i] - mean) * inv * gin[e] + bin[e];
                sEvo[row * 513 + e] = y;
                if (bid == 0) g_evolved[row * 512 + e] = y;
            }
        }
        __syncthreads();
        {   // warp: dd = w&15 (col in strip), kh = w>>4; lane = row
            int dd = w & 15, kh = w >> 4;
            int p = bid * 16 + dd;
            const float* xr = sEvo + lane * 513 + kh * 256;
            const float* wcol = Wa1 + (size_t)(kh * 256) * H_ + p;
            float a0 = 0.f, a1 = 0.f;
#pragma unroll 8
            for (int k = 0; k < 256; k += 2) {
                a0 = fmaf(xr[k], wcol[(size_t)k * H_], a0);
                a1 = fmaf(xr[k + 1], wcol[(size_t)(k + 1) * H_], a1);
            }
            sPart[kh * 512 + lane * 16 + dd] = a0 + a1;
        }
        __syncthreads();
        if (tid < 512) {
            int l = tid >> 4, dd = tid & 15;
            g_h1[l * H_ + bid * 16 + dd] = sPart[tid] + sPart[512 + tid];
        }
    }
    gbar();

    // ======== S7: mlp strip GEMM (block = (ks = bid&3, dseg = bid>>2))
    {
        float* sH = sm;               // 32 x 513
        float* sPart = sm + 16416;    // 1024
        int ks = bid & 3, dseg = bid >> 2;
        for (int i = tid; i < 16384; i += NT) {
            int row = i >> 9, k = i & 511;
            int kg = ks * 512 + k;
            sH[row * 513 + k] = fmaxf(g_h1[row * H_ + kg] + ba1[kg], 0.f);
        }
        __syncthreads();
        {
            int dd = w & 15, kh = w >> 4;
            int d = dseg * 16 + dd;
            const float* hr = sH + lane * 513 + kh * 256;
            const float* wcol = Wa2 + (size_t)(ks * 512 + kh * 256) * D_ + d;
            float a0 = 0.f, a1 = 0.f;
#pragma unroll 8
            for (int k = 0; k < 256; k += 2) {
                a0 = fmaf(hr[k], wcol[(size_t)k * D_], a0);
                a1 = fmaf(hr[k + 1], wcol[(size_t)(k + 1) * D_], a1);
            }
            sPart[kh * 512 + lane * 16 + dd] = a0 + a1;
        }
        __syncthreads();
        if (tid < 512) {
            int l = tid >> 4, dd = tid & 15;
            g_mlpp[ks * 16384 + l * 512 + dseg * 16 + dd] = sPart[tid] + sPart[512 + tid];
        }
    }
    gbar();

    // ======== S8+S9: LN2 (redundant, warp-per-row) + broadcast (all blocks)
    {
        float* sAl = sm;   // 16384
        {
            int row = w;
            float x[16];
            float s = 0.f;
#pragma unroll
            for (int i = 0; i < 16; i++) {
                int e = lane + 32 * i;
                int o = row * 512 + e;
                x[i] = g_evolved[o] + g_mlpp[o] + g_mlpp[16384 + o] +
                       g_mlpp[32768 + o] + g_mlpp[49152 + o] + ba2[e];
                s += x[i];
            }
            float mean = warp_sum(s) * (1.f / D_);
            float v = 0.f;
#pragma unroll
            for (int i = 0; i < 16; i++) { float d = x[i] - mean; v = fmaf(d, d, v); }
            float inv = rsqrtf(warp_sum(v) * (1.f / D_) + LN_EPS);
#pragma unroll
            for (int i = 0; i < 16; i++) {
                int e = lane + 32 * i;
                float y = (x[i] - mean) * inv * gout[e] + bout[e];
                sAl[row * 512 + e] = y;
                if (bid == 0) out[OFF_ALIGNED + row * 512 + e] = y;
            }
        }
        __syncthreads();
        {
            const float4 v = reinterpret_cast<const float4*>(sAl)[gtid & 4095];
            float4* dst = reinterpret_cast<float4*>(out + OFF_AP);
#pragma unroll 8
            for (int k2 = 0; k2 < 32; k2++) dst[gtid + k2 * NTH] = v;
        }
    }
}

// ---------------- launch ----------------
extern "C" void kernel_launch(void* const* d_in, const int* in_sizes, int n_in,
                              void* d_out, int out_size) {
    (void)in_sizes; (void)n_in; (void)out_size;
    const float* base = (const float*)d_in[0];
    const float* np_  = (const float*)d_in[1];
    const float* te   = (const float*)d_in[2];
    const float* Wt   = (const float*)d_in[3];
    const float* bt   = (const float*)d_in[4];
    const float* Wq   = (const float*)d_in[5];
    const float* bq   = (const float*)d_in[6];
    const float* Wk   = (const float*)d_in[7];
    const float* bk   = (const float*)d_in[8];
    const float* Wv   = (const float*)d_in[9];
    const float* bv   = (const float*)d_in[10];
    const float* Wo   = (const float*)d_in[11];
    const float* bo   = (const float*)d_in[12];
    const float* Wa1  = (const float*)d_in[13];
    const float* ba1  = (const float*)d_in[14];
    const float* Wa2  = (const float*)d_in[15];
    const float* ba2  = (const float*)d_in[16];
    const float* gin  = (const float*)d_in[17];
    const float* bin  = (const float*)d_in[18];
    const float* gout = (const float*)d_in[19];
    const float* bout = (const float*)d_in[20];
    float* out = (float*)d_out;

    static int attr_done = 0;
    if (!attr_done) {
        cudaFuncSetAttribute(mega, cudaFuncAttributeMaxDynamicSharedMemorySize, SMEM_BYTES);
        attr_done = 1;
    }
    mega<<<NB, NT, SMEM_BYTES>>>(base, np_, te, Wt, bt, Wq, bq, Wk, bk, Wv, bv,
                                 Wo, bo, Wa1, ba1, Wa2, ba2, gin, bin, gout, bout, out);
}